// round 1
// baseline (speedup 1.0000x reference)
#include <cuda_runtime.h>
#include <math.h>

#define B_   8
#define S_   512
#define HID_ 768
#define H_   12
#define D_   64
#define BS_  (B_*S_)          // 4096
#define BH_  (B_*H_)          // 96

#define CTX_ELEMS ((size_t)B_*S_*HID_)        // 3,145,728
#define SC_ELEMS  ((size_t)BH_*S_*S_)         // 25,165,824

// Scratch (device globals — no allocation in kernel_launch)
__device__ float g_q[BH_*S_*D_];
__device__ float g_k[BH_*S_*D_];
__device__ float g_v[BH_*S_*D_];
__device__ float g_p[BH_*S_*S_];

// ---------------------------------------------------------------------------
// Kernel 1: QKV projection.  out[b,h,s,d] = sum_k hid[m,k]*W[n,k] + bias[n]
// M=4096, N=768, K=768; block tile 128x128, BK=16, thread tile 8x8.
// grid: (N/128=6, M/128=32, 3), 256 threads.
// ---------------------------------------------------------------------------
__global__ void __launch_bounds__(256)
qkv_gemm(const float* __restrict__ hid,
         const float* __restrict__ Wq, const float* __restrict__ bq,
         const float* __restrict__ Wk, const float* __restrict__ bk,
         const float* __restrict__ Wv, const float* __restrict__ bv)
{
    const int z = blockIdx.z;
    const float* W    = (z == 0) ? Wq : ((z == 1) ? Wk : Wv);
    const float* bias = (z == 0) ? bq : ((z == 1) ? bk : bv);
    float* out        = (z == 0) ? g_q : ((z == 1) ? g_k : g_v);

    const int m0 = blockIdx.y * 128;
    const int n0 = blockIdx.x * 128;

    __shared__ float As[16][132];   // [k][m], padded; row stride 528B (16B aligned)
    __shared__ float Bs[16][132];   // [k][n]

    const int tid = threadIdx.x;
    const int tx  = tid & 15;       // 0..15 -> N
    const int ty  = tid >> 4;       // 0..15 -> M

    float acc[8][8];
    #pragma unroll
    for (int i = 0; i < 8; i++)
        #pragma unroll
        for (int j = 0; j < 8; j++)
            acc[i][j] = 0.0f;

    for (int k0 = 0; k0 < HID_; k0 += 16) {
        // load A tile 128x16 and B tile 128x16 (2 float4 each per thread)
        #pragma unroll
        for (int r = 0; r < 2; r++) {
            int i4  = tid + 256 * r;      // 0..511
            int row = i4 >> 2;            // 0..127
            int q   = i4 & 3;             // float4 index along K
            float4 a = *(const float4*)(hid + (size_t)(m0 + row) * HID_ + k0 + q * 4);
            As[q*4+0][row] = a.x; As[q*4+1][row] = a.y;
            As[q*4+2][row] = a.z; As[q*4+3][row] = a.w;
            float4 b = *(const float4*)(W + (size_t)(n0 + row) * HID_ + k0 + q * 4);
            Bs[q*4+0][row] = b.x; Bs[q*4+1][row] = b.y;
            Bs[q*4+2][row] = b.z; Bs[q*4+3][row] = b.w;
        }
        __syncthreads();

        #pragma unroll
        for (int kk = 0; kk < 16; kk++) {
            float4 a0 = *(const float4*)&As[kk][ty * 8];
            float4 a1 = *(const float4*)&As[kk][ty * 8 + 4];
            float4 b0 = *(const float4*)&Bs[kk][tx * 8];
            float4 b1 = *(const float4*)&Bs[kk][tx * 8 + 4];
            float av[8] = {a0.x, a0.y, a0.z, a0.w, a1.x, a1.y, a1.z, a1.w};
            float bw[8] = {b0.x, b0.y, b0.z, b0.w, b1.x, b1.y, b1.z, b1.w};
            #pragma unroll
            for (int i = 0; i < 8; i++)
                #pragma unroll
                for (int j = 0; j < 8; j++)
                    acc[i][j] = fmaf(av[i], bw[j], acc[i][j]);
        }
        __syncthreads();
    }

    // epilogue: add bias, write to [B,H,S,D]
    const int nbase = n0 + tx * 8;
    const int h  = nbase / D_;
    const int d0 = nbase % D_;          // 8-aligned, never crosses a head
    float bsv[8];
    #pragma unroll
    for (int j = 0; j < 8; j++) bsv[j] = bias[nbase + j];

    #pragma unroll
    for (int i = 0; i < 8; i++) {
        int m = m0 + ty * 8 + i;
        int b = m >> 9;                 // /512
        int s = m & 511;
        float* o = out + (((size_t)(b * H_ + h) * S_ + s) * D_ + d0);
        float4 v0 = make_float4(acc[i][0] + bsv[0], acc[i][1] + bsv[1],
                                acc[i][2] + bsv[2], acc[i][3] + bsv[3]);
        float4 v1 = make_float4(acc[i][4] + bsv[4], acc[i][5] + bsv[5],
                                acc[i][6] + bsv[6], acc[i][7] + bsv[7]);
        *(float4*)o       = v0;
        *(float4*)(o + 4) = v1;
    }
}

// ---------------------------------------------------------------------------
// Kernel 2: all 4 score tensors.  C[q,k] = 0.125*dot(X[q],Y[k]) + mask[b][k]
// Per batch (type, bh): M=N=512, K=64 fully resident. 64x64 tile, 4x4/thread.
// grid: (8, 8, 4*96), 256 threads.
// ---------------------------------------------------------------------------
__global__ void __launch_bounds__(256)
scores_gemm(const float* __restrict__ mask, float* __restrict__ out_base)
{
    const int z    = blockIdx.z;
    const int type = z / BH_;           // 0:qk 1:qq 2:kk 3:vv
    const int bh   = z % BH_;

    const float *X, *Y;
    if (type == 0)      { X = g_q; Y = g_k; }
    else if (type == 1) { X = g_q; Y = g_q; }
    else if (type == 2) { X = g_k; Y = g_k; }
    else                { X = g_v; Y = g_v; }
    X += (size_t)bh * S_ * D_;
    Y += (size_t)bh * S_ * D_;

    float* out = out_base + (size_t)type * SC_ELEMS + (size_t)bh * S_ * S_;
    const float* mrow = mask + (size_t)(bh / H_) * S_;

    const int m0 = blockIdx.y * 64;     // q rows
    const int n0 = blockIdx.x * 64;     // k cols

    __shared__ float Xs[64][68];        // [k][m]
    __shared__ float Ys[64][68];        // [k][n]

    const int tid = threadIdx.x;
    const int tx  = tid & 15;
    const int ty  = tid >> 4;

    // load both 64x64 tiles (4 float4 each per thread), transposed to [k][row]
    #pragma unroll
    for (int r = 0; r < 4; r++) {
        int i4  = tid + 256 * r;        // 0..1023
        int row = i4 >> 4;              // 0..63
        int q   = i4 & 15;              // float4 along D=64
        float4 a = *(const float4*)(X + (size_t)(m0 + row) * D_ + q * 4);
        Xs[q*4+0][row] = a.x; Xs[q*4+1][row] = a.y;
        Xs[q*4+2][row] = a.z; Xs[q*4+3][row] = a.w;
        float4 b = *(const float4*)(Y + (size_t)(n0 + row) * D_ + q * 4);
        Ys[q*4+0][row] = b.x; Ys[q*4+1][row] = b.y;
        Ys[q*4+2][row] = b.z; Ys[q*4+3][row] = b.w;
    }
    __syncthreads();

    float acc[4][4];
    #pragma unroll
    for (int i = 0; i < 4; i++)
        #pragma unroll
        for (int j = 0; j < 4; j++) acc[i][j] = 0.0f;

    #pragma unroll
    for (int kk = 0; kk < 64; kk++) {
        float4 a = *(const float4*)&Xs[kk][ty * 4];
        float4 b = *(const float4*)&Ys[kk][tx * 4];
        float av[4] = {a.x, a.y, a.z, a.w};
        float bw[4] = {b.x, b.y, b.z, b.w};
        #pragma unroll
        for (int i = 0; i < 4; i++)
            #pragma unroll
            for (int j = 0; j < 4; j++)
                acc[i][j] = fmaf(av[i], bw[j], acc[i][j]);
    }

    const int kc = n0 + tx * 4;
    float4 mv = *(const float4*)(mrow + kc);
    #pragma unroll
    for (int i = 0; i < 4; i++) {
        int qrow = m0 + ty * 4 + i;
        float4 o = make_float4(acc[i][0] * 0.125f + mv.x,
                               acc[i][1] * 0.125f + mv.y,
                               acc[i][2] * 0.125f + mv.z,
                               acc[i][3] * 0.125f + mv.w);
        *(float4*)(out + (size_t)qrow * S_ + kc) = o;
    }
}

// ---------------------------------------------------------------------------
// Kernel 3: row softmax of scores (qk) -> g_p.  One block per row of 512.
// ---------------------------------------------------------------------------
__global__ void __launch_bounds__(256)
softmax_k(const float* __restrict__ sc)
{
    const size_t row = blockIdx.x;
    const float* src = sc  + row * S_;
    float*       dst = g_p + row * S_;
    const int t = threadIdx.x;

    float v0 = src[t];
    float v1 = src[t + 256];

    __shared__ float red[8];
    __shared__ float red2[8];

    float m = fmaxf(v0, v1);
    #pragma unroll
    for (int o = 16; o > 0; o >>= 1)
        m = fmaxf(m, __shfl_xor_sync(0xffffffffu, m, o));
    if ((t & 31) == 0) red[t >> 5] = m;
    __syncthreads();
    float M = red[0];
    #pragma unroll
    for (int i = 1; i < 8; i++) M = fmaxf(M, red[i]);

    float e0 = expf(v0 - M);
    float e1 = expf(v1 - M);
    float s = e0 + e1;
    #pragma unroll
    for (int o = 16; o > 0; o >>= 1)
        s += __shfl_xor_sync(0xffffffffu, s, o);
    if ((t & 31) == 0) red2[t >> 5] = s;
    __syncthreads();
    float Ssum = 0.0f;
    #pragma unroll
    for (int i = 0; i < 8; i++) Ssum += red2[i];

    float inv = 1.0f / Ssum;
    dst[t]       = e0 * inv;
    dst[t + 256] = e1 * inv;
}

// ---------------------------------------------------------------------------
// Kernel 4: ctx = P @ V, written directly as [B,S,H*D].
// Per batch bh: M=512, N=64, K=512. 64x64 tile, BK=16, 4x4/thread.
// grid: (1, 8, 96), 256 threads.
// ---------------------------------------------------------------------------
__global__ void __launch_bounds__(256)
pv_gemm(float* __restrict__ ctx)
{
    const int bh = blockIdx.z;
    const int m0 = blockIdx.y * 64;
    const float* P = g_p + (size_t)bh * S_ * S_;
    const float* V = g_v + (size_t)bh * S_ * D_;
    const int b = bh / H_;
    const int h = bh % H_;

    __shared__ float Ps[16][68];    // [k][m]
    __shared__ float Vs[16][64];    // [k][d]

    const int tid = threadIdx.x;
    const int tx  = tid & 15;
    const int ty  = tid >> 4;

    float acc[4][4];
    #pragma unroll
    for (int i = 0; i < 4; i++)
        #pragma unroll
        for (int j = 0; j < 4; j++) acc[i][j] = 0.0f;

    for (int k0 = 0; k0 < S_; k0 += 16) {
        {   // P tile: 64 rows x 16 k -> 256 float4, 1 per thread
            int row = tid >> 2;
            int q   = tid & 3;
            float4 a = *(const float4*)(P + (size_t)(m0 + row) * S_ + k0 + q * 4);
            Ps[q*4+0][row] = a.x; Ps[q*4+1][row] = a.y;
            Ps[q*4+2][row] = a.z; Ps[q*4+3][row] = a.w;
        }
        {   // V tile: 16 k x 64 d -> natural layout
            int row = tid >> 4;
            int q   = tid & 15;
            *(float4*)&Vs[row][q * 4] =
                *(const float4*)(V + (size_t)(k0 + row) * D_ + q * 4);
        }
        __syncthreads();

        #pragma unroll
        for (int kk = 0; kk < 16; kk++) {
            float4 a = *(const float4*)&Ps[kk][ty * 4];
            float4 bq4 = *(const float4*)&Vs[kk][tx * 4];
            float av[4] = {a.x, a.y, a.z, a.w};
            float bw[4] = {bq4.x, bq4.y, bq4.z, bq4.w};
            #pragma unroll
            for (int i = 0; i < 4; i++)
                #pragma unroll
                for (int j = 0; j < 4; j++)
                    acc[i][j] = fmaf(av[i], bw[j], acc[i][j]);
        }
        __syncthreads();
    }

    #pragma unroll
    for (int i = 0; i < 4; i++) {
        int s = m0 + ty * 4 + i;
        float* o = ctx + ((size_t)(b * S_ + s) * HID_ + h * D_ + tx * 4);
        *(float4*)o = make_float4(acc[i][0], acc[i][1], acc[i][2], acc[i][3]);
    }
}

// ---------------------------------------------------------------------------
extern "C" void kernel_launch(void* const* d_in, const int* in_sizes, int n_in,
                              void* d_out, int out_size)
{
    const float* hid  = (const float*)d_in[0];
    const float* mask = (const float*)d_in[1];
    const float* Wq   = (const float*)d_in[2];
    const float* bq   = (const float*)d_in[3];
    const float* Wk   = (const float*)d_in[4];
    const float* bk   = (const float*)d_in[5];
    const float* Wv   = (const float*)d_in[6];
    const float* bv   = (const float*)d_in[7];
    float* out = (float*)d_out;

    // 1) Q,K,V projections -> [B,H,S,D] scratch
    qkv_gemm<<<dim3(HID_ / 128, BS_ / 128, 3), 256>>>(hid, Wq, bq, Wk, bk, Wv, bv);

    // 2) scores / scores_qq / scores_kk / scores_vv -> d_out (after ctx region)
    scores_gemm<<<dim3(S_ / 64, S_ / 64, 4 * BH_), 256>>>(mask, out + CTX_ELEMS);

    // 3) softmax of scores(qk) -> g_p
    softmax_k<<<BH_ * S_, 256>>>(out + CTX_ELEMS);

    // 4) ctx = P @ V -> d_out[0 .. CTX_ELEMS)
    pv_gemm<<<dim3(1, S_ / 64, BH_), 256>>>(out);
}

// round 2
// speedup vs baseline: 1.5755x; 1.5755x over previous
#include <cuda_runtime.h>
#include <math.h>
#include <stdint.h>

#define B_   8
#define S_   512
#define HID_ 768
#define H_   12
#define D_   64
#define BS_  (B_*S_)          // 4096
#define BH_  (B_*H_)          // 96

#define CTX_ELEMS ((size_t)B_*S_*HID_)        // 3,145,728
#define SC_ELEMS  ((size_t)BH_*S_*S_)         // 25,165,824

// Scratch (device globals — no allocation in kernel_launch)
__device__ float g_q[BH_*S_*D_];
__device__ float g_k[BH_*S_*D_];
__device__ float g_v[BH_*S_*D_];

__device__ __forceinline__ float to_tf32(float x) {
    float r;
    asm("cvt.rna.tf32.f32 %0, %1;" : "=f"(r) : "f"(x));
    return r;
}

// ---------------------------------------------------------------------------
// Kernel 1: QKV projection (fp32 FFMA — kept exact to bound total tf32 error).
// out[b,h,s,d] = sum_k hid[m,k]*W[n,k] + bias[n]
// M=4096, N=768, K=768; block tile 128x128, BK=16, thread tile 8x8.
// ---------------------------------------------------------------------------
__global__ void __launch_bounds__(256)
qkv_gemm(const float* __restrict__ hid,
         const float* __restrict__ Wq, const float* __restrict__ bq,
         const float* __restrict__ Wk, const float* __restrict__ bk,
         const float* __restrict__ Wv, const float* __restrict__ bv)
{
    const int z = blockIdx.z;
    const float* W    = (z == 0) ? Wq : ((z == 1) ? Wk : Wv);
    const float* bias = (z == 0) ? bq : ((z == 1) ? bk : bv);
    float* out        = (z == 0) ? g_q : ((z == 1) ? g_k : g_v);

    const int m0 = blockIdx.y * 128;
    const int n0 = blockIdx.x * 128;

    __shared__ float As[16][132];
    __shared__ float Bs[16][132];

    const int tid = threadIdx.x;
    const int tx  = tid & 15;
    const int ty  = tid >> 4;

    float acc[8][8];
    #pragma unroll
    for (int i = 0; i < 8; i++)
        #pragma unroll
        for (int j = 0; j < 8; j++)
            acc[i][j] = 0.0f;

    for (int k0 = 0; k0 < HID_; k0 += 16) {
        #pragma unroll
        for (int r = 0; r < 2; r++) {
            int i4  = tid + 256 * r;
            int row = i4 >> 2;
            int q   = i4 & 3;
            float4 a = *(const float4*)(hid + (size_t)(m0 + row) * HID_ + k0 + q * 4);
            As[q*4+0][row] = a.x; As[q*4+1][row] = a.y;
            As[q*4+2][row] = a.z; As[q*4+3][row] = a.w;
            float4 b = *(const float4*)(W + (size_t)(n0 + row) * HID_ + k0 + q * 4);
            Bs[q*4+0][row] = b.x; Bs[q*4+1][row] = b.y;
            Bs[q*4+2][row] = b.z; Bs[q*4+3][row] = b.w;
        }
        __syncthreads();

        #pragma unroll
        for (int kk = 0; kk < 16; kk++) {
            float4 a0 = *(const float4*)&As[kk][ty * 8];
            float4 a1 = *(const float4*)&As[kk][ty * 8 + 4];
            float4 b0 = *(const float4*)&Bs[kk][tx * 8];
            float4 b1 = *(const float4*)&Bs[kk][tx * 8 + 4];
            float av[8] = {a0.x, a0.y, a0.z, a0.w, a1.x, a1.y, a1.z, a1.w};
            float bw[8] = {b0.x, b0.y, b0.z, b0.w, b1.x, b1.y, b1.z, b1.w};
            #pragma unroll
            for (int i = 0; i < 8; i++)
                #pragma unroll
                for (int j = 0; j < 8; j++)
                    acc[i][j] = fmaf(av[i], bw[j], acc[i][j]);
        }
        __syncthreads();
    }

    const int nbase = n0 + tx * 8;
    const int h  = nbase / D_;
    const int d0 = nbase % D_;
    float bsv[8];
    #pragma unroll
    for (int j = 0; j < 8; j++) bsv[j] = bias[nbase + j];

    #pragma unroll
    for (int i = 0; i < 8; i++) {
        int m = m0 + ty * 8 + i;
        int b = m >> 9;
        int s = m & 511;
        float* o = out + (((size_t)(b * H_ + h) * S_ + s) * D_ + d0);
        float4 v0 = make_float4(acc[i][0] + bsv[0], acc[i][1] + bsv[1],
                                acc[i][2] + bsv[2], acc[i][3] + bsv[3]);
        float4 v1 = make_float4(acc[i][4] + bsv[4], acc[i][5] + bsv[5],
                                acc[i][6] + bsv[6], acc[i][7] + bsv[7]);
        *(float4*)o       = v0;
        *(float4*)(o + 4) = v1;
    }
}

// ---------------------------------------------------------------------------
// Kernel 2: all 4 score tensors via tf32 mma.sync (tensor pipe).
// C[q,k] = 0.125*dot(X[q],Y[k]) + mask[b][k]
// Block: 64x64 output tile, 128 threads (4 warps, 2x2 warp layout, 32x32 each).
// Warp: m16n8k8 tiles: 2(m) x 4(n) per k-step, 8 k-steps (K=64).
// grid: (8, 8, 4*96).
// ---------------------------------------------------------------------------
__global__ void __launch_bounds__(128)
scores_mma(const float* __restrict__ mask, float* __restrict__ out_base)
{
    const int z    = blockIdx.z;
    const int type = z / BH_;           // 0:qk 1:qq 2:kk 3:vv
    const int bh   = z - type * BH_;

    const float *X, *Y;
    if (type == 0)      { X = g_q; Y = g_k; }
    else if (type == 1) { X = g_q; Y = g_q; }
    else if (type == 2) { X = g_k; Y = g_k; }
    else                { X = g_v; Y = g_v; }
    X += (size_t)bh * S_ * D_;
    Y += (size_t)bh * S_ * D_;

    float* out = out_base + (size_t)type * SC_ELEMS + (size_t)bh * S_ * S_;
    const float* mrow = mask + (size_t)(bh / H_) * S_;

    const int m0 = blockIdx.y * 64;     // q rows
    const int n0 = blockIdx.x * 64;     // k cols

    __shared__ float Xs[64][68];        // [row][k], pad 4 -> conflict-free frags
    __shared__ float Ys[64][68];

    const int tid = threadIdx.x;

    // Load tiles, converting fp32 -> tf32 (rna) at smem store.
    #pragma unroll
    for (int r = 0; r < 8; r++) {
        int idx = tid + 128 * r;        // 0..1023
        int row = idx >> 4;
        int q   = idx & 15;
        float4 a = *(const float4*)(X + (size_t)(m0 + row) * D_ + q * 4);
        Xs[row][q*4+0] = to_tf32(a.x); Xs[row][q*4+1] = to_tf32(a.y);
        Xs[row][q*4+2] = to_tf32(a.z); Xs[row][q*4+3] = to_tf32(a.w);
        float4 b = *(const float4*)(Y + (size_t)(n0 + row) * D_ + q * 4);
        Ys[row][q*4+0] = to_tf32(b.x); Ys[row][q*4+1] = to_tf32(b.y);
        Ys[row][q*4+2] = to_tf32(b.z); Ys[row][q*4+3] = to_tf32(b.w);
    }
    __syncthreads();

    const int lane = tid & 31;
    const int wid  = tid >> 5;
    const int wm   = (wid & 1) * 32;
    const int wn   = (wid >> 1) * 32;
    const int gr   = lane >> 2;          // 0..7
    const int gc   = lane & 3;           // 0..3

    float c[2][4][4];
    #pragma unroll
    for (int im = 0; im < 2; im++)
        #pragma unroll
        for (int jn = 0; jn < 4; jn++)
            #pragma unroll
            for (int r = 0; r < 4; r++)
                c[im][jn][r] = 0.0f;

    #pragma unroll
    for (int k0 = 0; k0 < 64; k0 += 8) {
        uint32_t a[2][4], b[4][2];
        #pragma unroll
        for (int im = 0; im < 2; im++) {
            int r0 = wm + im * 16 + gr;
            a[im][0] = __float_as_uint(Xs[r0    ][k0 + gc    ]);
            a[im][1] = __float_as_uint(Xs[r0 + 8][k0 + gc    ]);
            a[im][2] = __float_as_uint(Xs[r0    ][k0 + gc + 4]);
            a[im][3] = __float_as_uint(Xs[r0 + 8][k0 + gc + 4]);
        }
        #pragma unroll
        for (int jn = 0; jn < 4; jn++) {
            int n = wn + jn * 8 + gr;
            b[jn][0] = __float_as_uint(Ys[n][k0 + gc    ]);
            b[jn][1] = __float_as_uint(Ys[n][k0 + gc + 4]);
        }
        #pragma unroll
        for (int im = 0; im < 2; im++)
            #pragma unroll
            for (int jn = 0; jn < 4; jn++) {
                asm volatile(
                    "mma.sync.aligned.m16n8k8.row.col.f32.tf32.tf32.f32 "
                    "{%0,%1,%2,%3}, {%4,%5,%6,%7}, {%8,%9}, {%0,%1,%2,%3};\n"
                    : "+f"(c[im][jn][0]), "+f"(c[im][jn][1]),
                      "+f"(c[im][jn][2]), "+f"(c[im][jn][3])
                    : "r"(a[im][0]), "r"(a[im][1]), "r"(a[im][2]), "r"(a[im][3]),
                      "r"(b[jn][0]), "r"(b[jn][1]));
            }
    }

    // Epilogue: scale + mask, fp32 writes.
    #pragma unroll
    for (int im = 0; im < 2; im++) {
        #pragma unroll
        for (int jn = 0; jn < 4; jn++) {
            int row = m0 + wm + im * 16 + gr;
            int col = n0 + wn + jn * 8 + gc * 2;
            float mv0 = mrow[col], mv1 = mrow[col + 1];
            float2 o0 = make_float2(c[im][jn][0] * 0.125f + mv0,
                                    c[im][jn][1] * 0.125f + mv1);
            float2 o1 = make_float2(c[im][jn][2] * 0.125f + mv0,
                                    c[im][jn][3] * 0.125f + mv1);
            *(float2*)(out + (size_t)row * S_ + col)       = o0;
            *(float2*)(out + (size_t)(row + 8) * S_ + col) = o1;
        }
    }
}

// ---------------------------------------------------------------------------
// Kernel 3: fused softmax + P@V (flash-style), reads qk scores from d_out,
// writes ctx directly as [B,S,H*D]. Saves the 200MB probs round-trip.
// Block: 64 q-rows x D=64, 256 threads, 8 k-tiles of 64.
// grid: (8, 96).
// ---------------------------------------------------------------------------
__global__ void __launch_bounds__(256)
pv_flash(const float* __restrict__ sc, float* __restrict__ ctx)
{
    const int bh = blockIdx.y;
    const int q0 = blockIdx.x * 64;
    const float* P = sc  + (size_t)bh * S_ * S_;
    const float* V = g_v + (size_t)bh * S_ * D_;
    const int b = bh / H_;
    const int h = bh - b * H_;

    __shared__ float Ssm[64][68];
    __shared__ float Vsm[64][68];
    __shared__ float rscale[64];
    __shared__ float rl[64];

    const int tid  = threadIdx.x;
    const int tx   = tid & 15;          // d cols (4 each)
    const int ty   = tid >> 4;          // q rows (4 each)
    const int srow = tid >> 2;          // stats: one row per quad
    const int sj   = tid & 3;

    float acc[4][4];
    #pragma unroll
    for (int i = 0; i < 4; i++)
        #pragma unroll
        for (int j = 0; j < 4; j++) acc[i][j] = 0.0f;

    float m_run = -1e30f;
    float l_run = 0.0f;

    for (int kt = 0; kt < 8; kt++) {
        // Load score tile [64q][64k] and V tile [64k][64d]
        #pragma unroll
        for (int r = 0; r < 4; r++) {
            int idx = tid + 256 * r;     // 0..1023
            int row = idx >> 4;
            int q   = idx & 15;
            *(float4*)&Ssm[row][q * 4] =
                *(const float4*)(P + (size_t)(q0 + row) * S_ + kt * 64 + q * 4);
            *(float4*)&Vsm[row][q * 4] =
                *(const float4*)(V + (size_t)(kt * 64 + row) * D_ + q * 4);
        }
        __syncthreads();

        // Row stats: quad (srow, sj) scans cols sj, sj+4, ... (conflict-free)
        float mx = -1e30f;
        #pragma unroll
        for (int cc = 0; cc < 16; cc++)
            mx = fmaxf(mx, Ssm[srow][sj + 4 * cc]);
        mx = fmaxf(mx, __shfl_xor_sync(0xffffffffu, mx, 1));
        mx = fmaxf(mx, __shfl_xor_sync(0xffffffffu, mx, 2));
        float m_new = fmaxf(m_run, mx);
        float scl   = __expf(m_run - m_new);   // first iter: exp(-huge)=0

        float ps = 0.0f;
        #pragma unroll
        for (int cc = 0; cc < 16; cc++) {
            float p = __expf(Ssm[srow][sj + 4 * cc] - m_new);
            Ssm[srow][sj + 4 * cc] = p;
            ps += p;
        }
        ps += __shfl_xor_sync(0xffffffffu, ps, 1);
        ps += __shfl_xor_sync(0xffffffffu, ps, 2);
        l_run = l_run * scl + ps;
        m_run = m_new;
        if (sj == 0) rscale[srow] = scl;
        __syncthreads();

        // Rescale accumulators, then acc += P_tile @ V_tile
        #pragma unroll
        for (int i = 0; i < 4; i++) {
            float s = rscale[ty * 4 + i];
            #pragma unroll
            for (int j = 0; j < 4; j++) acc[i][j] *= s;
        }
        #pragma unroll
        for (int kk = 0; kk < 64; kk++) {
            float4 bv = *(const float4*)&Vsm[kk][tx * 4];
            #pragma unroll
            for (int i = 0; i < 4; i++) {
                float av = Ssm[ty * 4 + i][kk];
                acc[i][0] = fmaf(av, bv.x, acc[i][0]);
                acc[i][1] = fmaf(av, bv.y, acc[i][1]);
                acc[i][2] = fmaf(av, bv.z, acc[i][2]);
                acc[i][3] = fmaf(av, bv.w, acc[i][3]);
            }
        }
        __syncthreads();
    }

    if (sj == 0) rl[srow] = l_run;
    __syncthreads();

    #pragma unroll
    for (int i = 0; i < 4; i++) {
        int s = q0 + ty * 4 + i;
        float inv = 1.0f / rl[ty * 4 + i];
        float* o = ctx + ((size_t)(b * S_ + s) * HID_ + h * D_ + tx * 4);
        *(float4*)o = make_float4(acc[i][0] * inv, acc[i][1] * inv,
                                  acc[i][2] * inv, acc[i][3] * inv);
    }
}

// ---------------------------------------------------------------------------
extern "C" void kernel_launch(void* const* d_in, const int* in_sizes, int n_in,
                              void* d_out, int out_size)
{
    const float* hid  = (const float*)d_in[0];
    const float* mask = (const float*)d_in[1];
    const float* Wq   = (const float*)d_in[2];
    const float* bq   = (const float*)d_in[3];
    const float* Wk   = (const float*)d_in[4];
    const float* bk   = (const float*)d_in[5];
    const float* Wv   = (const float*)d_in[6];
    const float* bv   = (const float*)d_in[7];
    float* out = (float*)d_out;

    // 1) Q,K,V projections -> [B,H,S,D] scratch (fp32, exact)
    qkv_gemm<<<dim3(HID_ / 128, BS_ / 128, 3), 256>>>(hid, Wq, bq, Wk, bk, Wv, bv);

    // 2) scores / scores_qq / scores_kk / scores_vv -> d_out (tf32 tensor cores)
    scores_mma<<<dim3(S_ / 64, S_ / 64, 4 * BH_), 128>>>(mask, out + CTX_ELEMS);

    // 3) fused softmax + P@V -> ctx in d_out[0 .. CTX_ELEMS)
    pv_flash<<<dim3(S_ / 64, BH_), 256>>>(out + CTX_ELEMS, out);
}

// round 3
// speedup vs baseline: 1.8141x; 1.1514x over previous
#include <cuda_runtime.h>
#include <math.h>
#include <stdint.h>

#define B_   8
#define S_   512
#define HID_ 768
#define H_   12
#define D_   64
#define BS_  (B_*S_)          // 4096
#define BH_  (B_*H_)          // 96

#define CTX_ELEMS ((size_t)B_*S_*HID_)        // 3,145,728
#define SC_ELEMS  ((size_t)BH_*S_*S_)         // 25,165,824

// Scratch (device globals — no allocation in kernel_launch)
__device__ float g_q[BH_*S_*D_];
__device__ float g_k[BH_*S_*D_];
__device__ float g_v[BH_*S_*D_];

__device__ __forceinline__ float to_tf32(float x) {
    float r;
    asm("cvt.rna.tf32.f32 %0, %1;" : "=f"(r) : "f"(x));
    return r;
}

__device__ __forceinline__ void split_tf32(float x, uint32_t& hi, uint32_t& lo) {
    float h;
    asm("cvt.rna.tf32.f32 %0, %1;" : "=f"(h) : "f"(x));
    float l = x - h;                    // exact in fp32 (hi has 13 zero low bits)
    float l2;
    asm("cvt.rna.tf32.f32 %0, %1;" : "=f"(l2) : "f"(l));
    hi = __float_as_uint(h);
    lo = __float_as_uint(l2);
}

__device__ __forceinline__ void mma_tf32(float* c, const uint32_t* a, const uint32_t* b) {
    asm volatile(
        "mma.sync.aligned.m16n8k8.row.col.f32.tf32.tf32.f32 "
        "{%0,%1,%2,%3}, {%4,%5,%6,%7}, {%8,%9}, {%0,%1,%2,%3};\n"
        : "+f"(c[0]), "+f"(c[1]), "+f"(c[2]), "+f"(c[3])
        : "r"(a[0]), "r"(a[1]), "r"(a[2]), "r"(a[3]), "r"(b[0]), "r"(b[1]));
}

__device__ __forceinline__ uint32_t smem_u32(const void* p) {
    return (uint32_t)__cvta_generic_to_shared(p);
}

__device__ __forceinline__ void cp16(uint32_t dst, const void* src) {
    asm volatile("cp.async.ca.shared.global [%0], [%1], 16;\n" :: "r"(dst), "l"(src));
}

// ---------------------------------------------------------------------------
// Kernel 1: QKV projection via 3xTF32 tensor-core GEMM (near-fp32 accuracy).
// out[b,h,s,d] = sum_k hid[m,k]*W[n,k] + bias[n]
// M=4096, N=768, K=768. Block tile 128(m) x 64(n), BK=16, cp.async double buf.
// 256 threads = 8 warps, layout 4(m) x 2(n), warp tile 32x32 of m16n8k8.
// grid: (12, 32, 3).
// ---------------------------------------------------------------------------
__global__ void __launch_bounds__(256, 2)
qkv_mma(const float* __restrict__ hid,
        const float* __restrict__ Wq, const float* __restrict__ bq,
        const float* __restrict__ Wk, const float* __restrict__ bk,
        const float* __restrict__ Wv, const float* __restrict__ bv)
{
    const int z = blockIdx.z;
    const float* W    = (z == 0) ? Wq : ((z == 1) ? Wk : Wv);
    const float* bias = (z == 0) ? bq : ((z == 1) ? bk : bv);
    float* out        = (z == 0) ? g_q : ((z == 1) ? g_k : g_v);

    const int m0 = blockIdx.y * 128;
    const int n0 = blockIdx.x * 64;

    // stride 20 floats: LDS fragment pattern (4*gr + gc) stays conflict-free
    __shared__ float As[2][128][20];
    __shared__ float Bs[2][64][20];

    const int tid  = threadIdx.x;
    const int lane = tid & 31;
    const int wid  = tid >> 5;
    const int gr   = lane >> 2;
    const int gc   = lane & 3;
    const int wm   = (wid & 3) * 32;
    const int wn   = (wid >> 2) * 32;

    float c[2][4][4];
    #pragma unroll
    for (int im = 0; im < 2; im++)
        #pragma unroll
        for (int jn = 0; jn < 4; jn++)
            #pragma unroll
            for (int r = 0; r < 4; r++) c[im][jn][r] = 0.0f;

    // --- async stage loader: A 128x16 (512 f4, 2/thread), B 64x16 (256 f4) ---
    #define LOAD_STAGE(buf, k0)                                                  \
    {                                                                            \
        _Pragma("unroll")                                                        \
        for (int r = 0; r < 2; r++) {                                            \
            int f = tid + 256 * r; int row = f >> 2; int q = f & 3;              \
            cp16(smem_u32(&As[buf][row][q * 4]),                                 \
                 hid + (size_t)(m0 + row) * HID_ + (k0) + q * 4);                \
        }                                                                        \
        { int row = tid >> 2; int q = tid & 3;                                   \
          cp16(smem_u32(&Bs[buf][row][q * 4]),                                   \
               W + (size_t)(n0 + row) * HID_ + (k0) + q * 4); }                  \
        asm volatile("cp.async.commit_group;\n");                                \
    }

    LOAD_STAGE(0, 0)

    const int NIT = HID_ / 16;   // 48
    for (int it = 0; it < NIT; it++) {
        if (it + 1 < NIT) {
            LOAD_STAGE((it + 1) & 1, (it + 1) * 16)
            asm volatile("cp.async.wait_group 1;\n");
        } else {
            asm volatile("cp.async.wait_group 0;\n");
        }
        __syncthreads();

        const int buf = it & 1;
        #pragma unroll
        for (int ks = 0; ks < 16; ks += 8) {
            uint32_t ahi[2][4], alo[2][4];
            #pragma unroll
            for (int im = 0; im < 2; im++) {
                int r = wm + im * 16 + gr;
                split_tf32(As[buf][r    ][ks + gc    ], ahi[im][0], alo[im][0]);
                split_tf32(As[buf][r + 8][ks + gc    ], ahi[im][1], alo[im][1]);
                split_tf32(As[buf][r    ][ks + gc + 4], ahi[im][2], alo[im][2]);
                split_tf32(As[buf][r + 8][ks + gc + 4], ahi[im][3], alo[im][3]);
            }
            uint32_t bhi[4][2], blo[4][2];
            #pragma unroll
            for (int jn = 0; jn < 4; jn++) {
                int n = wn + jn * 8 + gr;
                split_tf32(Bs[buf][n][ks + gc    ], bhi[jn][0], blo[jn][0]);
                split_tf32(Bs[buf][n][ks + gc + 4], bhi[jn][1], blo[jn][1]);
            }
            #pragma unroll
            for (int im = 0; im < 2; im++)
                #pragma unroll
                for (int jn = 0; jn < 4; jn++) {
                    mma_tf32(c[im][jn], ahi[im], bhi[jn]);   // hi*hi
                    mma_tf32(c[im][jn], ahi[im], blo[jn]);   // hi*lo
                    mma_tf32(c[im][jn], alo[im], bhi[jn]);   // lo*hi
                }
        }
        __syncthreads();
    }

    // Epilogue: + bias, scatter to [B,H,S,D]. Block n-tile == one head.
    const int h = n0 / D_;
    #pragma unroll
    for (int jn = 0; jn < 4; jn++) {
        int d = wn + jn * 8 + gc * 2;
        float b0 = bias[n0 + d], b1 = bias[n0 + d + 1];
        #pragma unroll
        for (int im = 0; im < 2; im++) {
            int m = m0 + wm + im * 16 + gr;
            int b = m >> 9;
            int s = m & 511;
            float* o = out + (((size_t)(b * H_ + h) * S_ + s) * D_ + d);
            *(float2*)o = make_float2(c[im][jn][0] + b0, c[im][jn][1] + b1);
            *(float2*)(o + 8 * D_) = make_float2(c[im][jn][2] + b0, c[im][jn][3] + b1);
        }
    }
    #undef LOAD_STAGE
}

// ---------------------------------------------------------------------------
// Kernel 2: all 4 score tensors via tf32 mma. C = 0.125*X@Y^T + mask.
// Block: 64(q) x 128(k) tile, 256 threads (8 warps 2x4, 32x32 each).
// grid: (4, 8, 4*96).
// ---------------------------------------------------------------------------
__global__ void __launch_bounds__(256)
scores_mma(const float* __restrict__ mask, float* __restrict__ out_base)
{
    const int z    = blockIdx.z;
    const int type = z / BH_;           // 0:qk 1:qq 2:kk 3:vv
    const int bh   = z - type * BH_;

    const float *X, *Y;
    if (type == 0)      { X = g_q; Y = g_k; }
    else if (type == 1) { X = g_q; Y = g_q; }
    else if (type == 2) { X = g_k; Y = g_k; }
    else                { X = g_v; Y = g_v; }
    X += (size_t)bh * S_ * D_;
    Y += (size_t)bh * S_ * D_;

    float* out = out_base + (size_t)type * SC_ELEMS + (size_t)bh * S_ * S_;
    const float* mrow = mask + (size_t)(bh / H_) * S_;

    const int m0 = blockIdx.y * 64;     // q rows
    const int n0 = blockIdx.x * 128;    // k cols

    __shared__ float Xs[64][68];
    __shared__ float Ys[128][68];

    const int tid = threadIdx.x;

    // Load tiles, fp32 -> tf32 at smem store (single quant, same as R2).
    #pragma unroll
    for (int r = 0; r < 4; r++) {
        int idx = tid + 256 * r;        // 0..1023
        int row = idx >> 4;
        int q   = idx & 15;
        float4 a = *(const float4*)(X + (size_t)(m0 + row) * D_ + q * 4);
        Xs[row][q*4+0] = to_tf32(a.x); Xs[row][q*4+1] = to_tf32(a.y);
        Xs[row][q*4+2] = to_tf32(a.z); Xs[row][q*4+3] = to_tf32(a.w);
    }
    #pragma unroll
    for (int r = 0; r < 8; r++) {
        int idx = tid + 256 * r;        // 0..2047
        int row = idx >> 4;
        int q   = idx & 15;
        float4 b = *(const float4*)(Y + (size_t)(n0 + row) * D_ + q * 4);
        Ys[row][q*4+0] = to_tf32(b.x); Ys[row][q*4+1] = to_tf32(b.y);
        Ys[row][q*4+2] = to_tf32(b.z); Ys[row][q*4+3] = to_tf32(b.w);
    }
    __syncthreads();

    const int lane = tid & 31;
    const int wid  = tid >> 5;
    const int wm   = (wid & 1) * 32;
    const int wn   = (wid >> 1) * 32;
    const int gr   = lane >> 2;
    const int gc   = lane & 3;

    float c[2][4][4];
    #pragma unroll
    for (int im = 0; im < 2; im++)
        #pragma unroll
        for (int jn = 0; jn < 4; jn++)
            #pragma unroll
            for (int r = 0; r < 4; r++) c[im][jn][r] = 0.0f;

    #pragma unroll
    for (int k0 = 0; k0 < 64; k0 += 8) {
        uint32_t a[2][4], b[4][2];
        #pragma unroll
        for (int im = 0; im < 2; im++) {
            int r0 = wm + im * 16 + gr;
            a[im][0] = __float_as_uint(Xs[r0    ][k0 + gc    ]);
            a[im][1] = __float_as_uint(Xs[r0 + 8][k0 + gc    ]);
            a[im][2] = __float_as_uint(Xs[r0    ][k0 + gc + 4]);
            a[im][3] = __float_as_uint(Xs[r0 + 8][k0 + gc + 4]);
        }
        #pragma unroll
        for (int jn = 0; jn < 4; jn++) {
            int n = wn + jn * 8 + gr;
            b[jn][0] = __float_as_uint(Ys[n][k0 + gc    ]);
            b[jn][1] = __float_as_uint(Ys[n][k0 + gc + 4]);
        }
        #pragma unroll
        for (int im = 0; im < 2; im++)
            #pragma unroll
            for (int jn = 0; jn < 4; jn++)
                mma_tf32(c[im][jn], a[im], b[jn]);
    }

    // Epilogue: scale + mask.
    #pragma unroll
    for (int im = 0; im < 2; im++) {
        #pragma unroll
        for (int jn = 0; jn < 4; jn++) {
            int row = m0 + wm + im * 16 + gr;
            int col = n0 + wn + jn * 8 + gc * 2;
            float mv0 = mrow[col], mv1 = mrow[col + 1];
            float2 o0 = make_float2(c[im][jn][0] * 0.125f + mv0,
                                    c[im][jn][1] * 0.125f + mv1);
            float2 o1 = make_float2(c[im][jn][2] * 0.125f + mv0,
                                    c[im][jn][3] * 0.125f + mv1);
            *(float2*)(out + (size_t)row * S_ + col)       = o0;
            *(float2*)(out + (size_t)(row + 8) * S_ + col) = o1;
        }
    }
}

// ---------------------------------------------------------------------------
// Kernel 3: fused softmax + P@V (flash-style), reads qk scores from d_out,
// writes ctx directly as [B,S,H*D].
// ---------------------------------------------------------------------------
__global__ void __launch_bounds__(256)
pv_flash(const float* __restrict__ sc, float* __restrict__ ctx)
{
    const int bh = blockIdx.y;
    const int q0 = blockIdx.x * 64;
    const float* P = sc  + (size_t)bh * S_ * S_;
    const float* V = g_v + (size_t)bh * S_ * D_;
    const int b = bh / H_;
    const int h = bh - b * H_;

    __shared__ float Ssm[64][68];
    __shared__ float Vsm[64][68];
    __shared__ float rscale[64];
    __shared__ float rl[64];

    const int tid  = threadIdx.x;
    const int tx   = tid & 15;
    const int ty   = tid >> 4;
    const int srow = tid >> 2;
    const int sj   = tid & 3;

    float acc[4][4];
    #pragma unroll
    for (int i = 0; i < 4; i++)
        #pragma unroll
        for (int j = 0; j < 4; j++) acc[i][j] = 0.0f;

    float m_run = -1e30f;
    float l_run = 0.0f;

    for (int kt = 0; kt < 8; kt++) {
        #pragma unroll
        for (int r = 0; r < 4; r++) {
            int idx = tid + 256 * r;
            int row = idx >> 4;
            int q   = idx & 15;
            *(float4*)&Ssm[row][q * 4] =
                *(const float4*)(P + (size_t)(q0 + row) * S_ + kt * 64 + q * 4);
            *(float4*)&Vsm[row][q * 4] =
                *(const float4*)(V + (size_t)(kt * 64 + row) * D_ + q * 4);
        }
        __syncthreads();

        float mx = -1e30f;
        #pragma unroll
        for (int cc = 0; cc < 16; cc++)
            mx = fmaxf(mx, Ssm[srow][sj + 4 * cc]);
        mx = fmaxf(mx, __shfl_xor_sync(0xffffffffu, mx, 1));
        mx = fmaxf(mx, __shfl_xor_sync(0xffffffffu, mx, 2));
        float m_new = fmaxf(m_run, mx);
        float scl   = __expf(m_run - m_new);

        float ps = 0.0f;
        #pragma unroll
        for (int cc = 0; cc < 16; cc++) {
            float p = __expf(Ssm[srow][sj + 4 * cc] - m_new);
            Ssm[srow][sj + 4 * cc] = p;
            ps += p;
        }
        ps += __shfl_xor_sync(0xffffffffu, ps, 1);
        ps += __shfl_xor_sync(0xffffffffu, ps, 2);
        l_run = l_run * scl + ps;
        m_run = m_new;
        if (sj == 0) rscale[srow] = scl;
        __syncthreads();

        #pragma unroll
        for (int i = 0; i < 4; i++) {
            float s = rscale[ty * 4 + i];
            #pragma unroll
            for (int j = 0; j < 4; j++) acc[i][j] *= s;
        }
        #pragma unroll
        for (int kk = 0; kk < 64; kk++) {
            float4 bv = *(const float4*)&Vsm[kk][tx * 4];
            #pragma unroll
            for (int i = 0; i < 4; i++) {
                float av = Ssm[ty * 4 + i][kk];
                acc[i][0] = fmaf(av, bv.x, acc[i][0]);
                acc[i][1] = fmaf(av, bv.y, acc[i][1]);
                acc[i][2] = fmaf(av, bv.z, acc[i][2]);
                acc[i][3] = fmaf(av, bv.w, acc[i][3]);
            }
        }
        __syncthreads();
    }

    if (sj == 0) rl[srow] = l_run;
    __syncthreads();

    #pragma unroll
    for (int i = 0; i < 4; i++) {
        int s = q0 + ty * 4 + i;
        float inv = 1.0f / rl[ty * 4 + i];
        float* o = ctx + ((size_t)(b * S_ + s) * HID_ + h * D_ + tx * 4);
        *(float4*)o = make_float4(acc[i][0] * inv, acc[i][1] * inv,
                                  acc[i][2] * inv, acc[i][3] * inv);
    }
}

// ---------------------------------------------------------------------------
extern "C" void kernel_launch(void* const* d_in, const int* in_sizes, int n_in,
                              void* d_out, int out_size)
{
    const float* hid  = (const float*)d_in[0];
    const float* mask = (const float*)d_in[1];
    const float* Wq   = (const float*)d_in[2];
    const float* bq   = (const float*)d_in[3];
    const float* Wk   = (const float*)d_in[4];
    const float* bk   = (const float*)d_in[5];
    const float* Wv   = (const float*)d_in[6];
    const float* bv   = (const float*)d_in[7];
    float* out = (float*)d_out;

    // 1) Q,K,V projections -> [B,H,S,D] scratch (3xTF32 tensor cores, ~fp32 exact)
    qkv_mma<<<dim3(HID_ / 64, BS_ / 128, 3), 256>>>(hid, Wq, bq, Wk, bk, Wv, bv);

    // 2) scores / scores_qq / scores_kk / scores_vv -> d_out (tf32 tensor cores)
    scores_mma<<<dim3(S_ / 128, S_ / 64, 4 * BH_), 256>>>(mask, out + CTX_ELEMS);

    // 3) fused softmax + P@V -> ctx in d_out[0 .. CTX_ELEMS)
    pv_flash<<<dim3(S_ / 64, BH_), 256>>>(out + CTX_ELEMS, out);
}

// round 4
// speedup vs baseline: 1.9721x; 1.0871x over previous
#include <cuda_runtime.h>
#include <math.h>
#include <stdint.h>

#define B_   8
#define S_   512
#define HID_ 768
#define H_   12
#define D_   64
#define BS_  (B_*S_)          // 4096
#define BH_  (B_*H_)          // 96

#define CTX_ELEMS ((size_t)B_*S_*HID_)        // 3,145,728
#define SC_ELEMS  ((size_t)BH_*S_*S_)         // 25,165,824

// Scratch (device globals — no allocation in kernel_launch)
__device__ float g_q[BH_*S_*D_];
__device__ float g_k[BH_*S_*D_];
__device__ float g_v[BH_*S_*D_];

__device__ __forceinline__ float to_tf32(float x) {
    float r;
    asm("cvt.rna.tf32.f32 %0, %1;" : "=f"(r) : "f"(x));
    return r;
}

__device__ __forceinline__ void split_tf32(float x, float& hi, float& lo) {
    float h;
    asm("cvt.rna.tf32.f32 %0, %1;" : "=f"(h) : "f"(x));
    float l = x - h;                    // exact in fp32
    asm("cvt.rna.tf32.f32 %0, %1;" : "=f"(lo) : "f"(l));
    hi = h;
}

__device__ __forceinline__ void mma_tf32(float* c, const uint32_t* a, const uint32_t* b) {
    asm volatile(
        "mma.sync.aligned.m16n8k8.row.col.f32.tf32.tf32.f32 "
        "{%0,%1,%2,%3}, {%4,%5,%6,%7}, {%8,%9}, {%0,%1,%2,%3};\n"
        : "+f"(c[0]), "+f"(c[1]), "+f"(c[2]), "+f"(c[3])
        : "r"(a[0]), "r"(a[1]), "r"(a[2]), "r"(a[3]), "r"(b[0]), "r"(b[1]));
}

// ---------------------------------------------------------------------------
// Kernel 1: QKV projection via 3xTF32 MMA, hi/lo split done ONCE at load.
// M=4096, N=768, K=768. Block 128(m) x 64(n), BK=16, reg double-buffer.
// 256 threads = 8 warps (4m x 2n), warp tile 32x32.
// grid: (12, 32, 3).
// ---------------------------------------------------------------------------
__global__ void __launch_bounds__(256, 2)
qkv_mma(const float* __restrict__ hid,
        const float* __restrict__ Wq, const float* __restrict__ bq,
        const float* __restrict__ Wk, const float* __restrict__ bk,
        const float* __restrict__ Wv, const float* __restrict__ bv)
{
    const int z = blockIdx.z;
    const float* W    = (z == 0) ? Wq : ((z == 1) ? Wk : Wv);
    const float* bias = (z == 0) ? bq : ((z == 1) ? bk : bv);
    float* out        = (z == 0) ? g_q : ((z == 1) ? g_k : g_v);

    const int m0 = blockIdx.y * 128;
    const int n0 = blockIdx.x * 64;

    __shared__ float Ah[2][128][20];
    __shared__ float Al[2][128][20];
    __shared__ float Bh[2][64][20];
    __shared__ float Bl[2][64][20];

    const int tid  = threadIdx.x;
    const int lane = tid & 31;
    const int wid  = tid >> 5;
    const int gr   = lane >> 2;
    const int gc   = lane & 3;
    const int wm   = (wid & 3) * 32;
    const int wn   = (wid >> 2) * 32;

    const int lrow = tid >> 2;          // 0..63
    const int lq   = (tid & 3) * 4;     // 0,4,8,12 (col within BK=16)

    float c[2][4][4];
    #pragma unroll
    for (int im = 0; im < 2; im++)
        #pragma unroll
        for (int jn = 0; jn < 4; jn++)
            #pragma unroll
            for (int r = 0; r < 4; r++) c[im][jn][r] = 0.0f;

    float4 ra0, ra1, rb;

    #define LDG_TILE(k0)                                                        \
        ra0 = *(const float4*)(hid + (size_t)(m0 + lrow)      * HID_ + (k0) + lq); \
        ra1 = *(const float4*)(hid + (size_t)(m0 + lrow + 64) * HID_ + (k0) + lq); \
        rb  = *(const float4*)(W   + (size_t)(n0 + lrow)      * HID_ + (k0) + lq);

    #define STS_SPLIT(buf)                                                      \
    {                                                                           \
        float h0,l0,h1,l1,h2,l2,h3,l3;                                          \
        split_tf32(ra0.x,h0,l0); split_tf32(ra0.y,h1,l1);                       \
        split_tf32(ra0.z,h2,l2); split_tf32(ra0.w,h3,l3);                       \
        *(float4*)&Ah[buf][lrow][lq] = make_float4(h0,h1,h2,h3);                \
        *(float4*)&Al[buf][lrow][lq] = make_float4(l0,l1,l2,l3);                \
        split_tf32(ra1.x,h0,l0); split_tf32(ra1.y,h1,l1);                       \
        split_tf32(ra1.z,h2,l2); split_tf32(ra1.w,h3,l3);                       \
        *(float4*)&Ah[buf][lrow+64][lq] = make_float4(h0,h1,h2,h3);             \
        *(float4*)&Al[buf][lrow+64][lq] = make_float4(l0,l1,l2,l3);             \
        split_tf32(rb.x,h0,l0); split_tf32(rb.y,h1,l1);                         \
        split_tf32(rb.z,h2,l2); split_tf32(rb.w,h3,l3);                         \
        *(float4*)&Bh[buf][lrow][lq] = make_float4(h0,h1,h2,h3);                \
        *(float4*)&Bl[buf][lrow][lq] = make_float4(l0,l1,l2,l3);                \
    }

    LDG_TILE(0)
    STS_SPLIT(0)
    __syncthreads();

    const int NIT = HID_ / 16;   // 48
    for (int it = 0; it < NIT; it++) {
        const int buf = it & 1;
        if (it + 1 < NIT) { LDG_TILE((it + 1) * 16) }

        #pragma unroll
        for (int ks = 0; ks < 16; ks += 8) {
            uint32_t ahi[2][4], alo[2][4], bhi[4][2], blo[4][2];
            #pragma unroll
            for (int im = 0; im < 2; im++) {
                int r = wm + im * 16 + gr;
                ahi[im][0] = __float_as_uint(Ah[buf][r    ][ks + gc    ]);
                ahi[im][1] = __float_as_uint(Ah[buf][r + 8][ks + gc    ]);
                ahi[im][2] = __float_as_uint(Ah[buf][r    ][ks + gc + 4]);
                ahi[im][3] = __float_as_uint(Ah[buf][r + 8][ks + gc + 4]);
                alo[im][0] = __float_as_uint(Al[buf][r    ][ks + gc    ]);
                alo[im][1] = __float_as_uint(Al[buf][r + 8][ks + gc    ]);
                alo[im][2] = __float_as_uint(Al[buf][r    ][ks + gc + 4]);
                alo[im][3] = __float_as_uint(Al[buf][r + 8][ks + gc + 4]);
            }
            #pragma unroll
            for (int jn = 0; jn < 4; jn++) {
                int n = wn + jn * 8 + gr;
                bhi[jn][0] = __float_as_uint(Bh[buf][n][ks + gc    ]);
                bhi[jn][1] = __float_as_uint(Bh[buf][n][ks + gc + 4]);
                blo[jn][0] = __float_as_uint(Bl[buf][n][ks + gc    ]);
                blo[jn][1] = __float_as_uint(Bl[buf][n][ks + gc + 4]);
            }
            #pragma unroll
            for (int im = 0; im < 2; im++)
                #pragma unroll
                for (int jn = 0; jn < 4; jn++) {
                    mma_tf32(c[im][jn], ahi[im], bhi[jn]);
                    mma_tf32(c[im][jn], ahi[im], blo[jn]);
                    mma_tf32(c[im][jn], alo[im], bhi[jn]);
                }
        }

        if (it + 1 < NIT) { STS_SPLIT((it + 1) & 1) }
        __syncthreads();
    }
    #undef LDG_TILE
    #undef STS_SPLIT

    // Epilogue: + bias, scatter to [B,H,S,D]. Block n-tile == one head.
    const int h = n0 / D_;
    #pragma unroll
    for (int jn = 0; jn < 4; jn++) {
        int d = wn + jn * 8 + gc * 2;
        float b0 = bias[n0 + d], b1 = bias[n0 + d + 1];
        #pragma unroll
        for (int im = 0; im < 2; im++) {
            int m = m0 + wm + im * 16 + gr;
            int b = m >> 9;
            int s = m & 511;
            float* o = out + (((size_t)(b * H_ + h) * S_ + s) * D_ + d);
            *(float2*)o = make_float2(c[im][jn][0] + b0, c[im][jn][1] + b1);
            *(float2*)(o + 8 * D_) = make_float2(c[im][jn][2] + b0, c[im][jn][3] + b1);
        }
    }
}

// ---------------------------------------------------------------------------
// Kernel 2: self-similarity scores (qq, kk, vv) via tf32 mma.
// C = 0.125*X@X^T + mask. Block: 64(q) x 128(k), 256 threads (8 warps 2x4).
// grid: (4, 8, 3*96).
// ---------------------------------------------------------------------------
__global__ void __launch_bounds__(256)
scores_sim(const float* __restrict__ mask, float* __restrict__ out_base)
{
    const int z    = blockIdx.z;
    const int type = 1 + z / BH_;       // 1:qq 2:kk 3:vv
    const int bh   = z % BH_;

    const float* X = (type == 1) ? g_q : ((type == 2) ? g_k : g_v);
    X += (size_t)bh * S_ * D_;

    float* out = out_base + (size_t)type * SC_ELEMS + (size_t)bh * S_ * S_;
    const float* mrow = mask + (size_t)(bh / H_) * S_;

    const int m0 = blockIdx.y * 64;
    const int n0 = blockIdx.x * 128;

    __shared__ float Xs[64][68];
    __shared__ float Ys[128][68];

    const int tid = threadIdx.x;

    #pragma unroll
    for (int r = 0; r < 4; r++) {
        int idx = tid + 256 * r;
        int row = idx >> 4;
        int q   = idx & 15;
        float4 a = *(const float4*)(X + (size_t)(m0 + row) * D_ + q * 4);
        Xs[row][q*4+0] = to_tf32(a.x); Xs[row][q*4+1] = to_tf32(a.y);
        Xs[row][q*4+2] = to_tf32(a.z); Xs[row][q*4+3] = to_tf32(a.w);
    }
    #pragma unroll
    for (int r = 0; r < 8; r++) {
        int idx = tid + 256 * r;
        int row = idx >> 4;
        int q   = idx & 15;
        float4 b = *(const float4*)(X + (size_t)(n0 + row) * D_ + q * 4);
        Ys[row][q*4+0] = to_tf32(b.x); Ys[row][q*4+1] = to_tf32(b.y);
        Ys[row][q*4+2] = to_tf32(b.z); Ys[row][q*4+3] = to_tf32(b.w);
    }
    __syncthreads();

    const int lane = tid & 31;
    const int wid  = tid >> 5;
    const int wm   = (wid & 1) * 32;
    const int wn   = (wid >> 1) * 32;
    const int gr   = lane >> 2;
    const int gc   = lane & 3;

    float c[2][4][4];
    #pragma unroll
    for (int im = 0; im < 2; im++)
        #pragma unroll
        for (int jn = 0; jn < 4; jn++)
            #pragma unroll
            for (int r = 0; r < 4; r++) c[im][jn][r] = 0.0f;

    #pragma unroll
    for (int k0 = 0; k0 < 64; k0 += 8) {
        uint32_t a[2][4], b[4][2];
        #pragma unroll
        for (int im = 0; im < 2; im++) {
            int r0 = wm + im * 16 + gr;
            a[im][0] = __float_as_uint(Xs[r0    ][k0 + gc    ]);
            a[im][1] = __float_as_uint(Xs[r0 + 8][k0 + gc    ]);
            a[im][2] = __float_as_uint(Xs[r0    ][k0 + gc + 4]);
            a[im][3] = __float_as_uint(Xs[r0 + 8][k0 + gc + 4]);
        }
        #pragma unroll
        for (int jn = 0; jn < 4; jn++) {
            int n = wn + jn * 8 + gr;
            b[jn][0] = __float_as_uint(Ys[n][k0 + gc    ]);
            b[jn][1] = __float_as_uint(Ys[n][k0 + gc + 4]);
        }
        #pragma unroll
        for (int im = 0; im < 2; im++)
            #pragma unroll
            for (int jn = 0; jn < 4; jn++)
                mma_tf32(c[im][jn], a[im], b[jn]);
    }

    #pragma unroll
    for (int im = 0; im < 2; im++) {
        #pragma unroll
        for (int jn = 0; jn < 4; jn++) {
            int row = m0 + wm + im * 16 + gr;
            int col = n0 + wn + jn * 8 + gc * 2;
            float mv0 = mrow[col], mv1 = mrow[col + 1];
            float2 o0 = make_float2(c[im][jn][0] * 0.125f + mv0,
                                    c[im][jn][1] * 0.125f + mv1);
            float2 o1 = make_float2(c[im][jn][2] * 0.125f + mv0,
                                    c[im][jn][3] * 0.125f + mv1);
            *(float2*)(out + (size_t)row * S_ + col)       = o0;
            *(float2*)(out + (size_t)(row + 8) * S_ + col) = o1;
        }
    }
}

// ---------------------------------------------------------------------------
// Kernel 3: fused qk-scores + softmax + P@V, all-MMA (tf32).
// Per block: 64 q-rows of one (b,h). Writes scores(qk) tile AND ctx.
// 128 threads = 4 warps; warp w owns rows [16w,16w+16) — softmax reductions
// are intra-quad shuffles only. grid: (8, 96).
// ---------------------------------------------------------------------------
__global__ void __launch_bounds__(128)
flash_attn(const float* __restrict__ mask, float* __restrict__ sout_base,
           float* __restrict__ ctx)
{
    const int bh = blockIdx.y;
    const int q0 = blockIdx.x * 64;
    const int b  = bh / H_;
    const int h  = bh - b * H_;
    const float* Qp = g_q + (size_t)bh * S_ * D_;
    const float* Kp = g_k + (size_t)bh * S_ * D_;
    const float* Vp = g_v + (size_t)bh * S_ * D_;
    float* sout = sout_base + (size_t)bh * S_ * S_;
    const float* mrow = mask + (size_t)b * S_;

    __shared__ float QPs[64][68];   // Q tile, then reused as P tile
    __shared__ float Ks[64][68];
    __shared__ float Vs[64][72];    // stride 72: conflict-free V^T B-frag loads

    const int tid  = threadIdx.x;
    const int lane = tid & 31;
    const int w    = tid >> 5;
    const int gr   = lane >> 2;
    const int gc   = lane & 3;

    // Load Q tile (tf32) and keep A-fragments in registers for all 8 k-tiles.
    #pragma unroll
    for (int r = 0; r < 8; r++) {
        int idx = tid + 128 * r;
        int row = idx >> 4;
        int q   = idx & 15;
        float4 a = *(const float4*)(Qp + (size_t)(q0 + row) * D_ + q * 4);
        QPs[row][q*4+0] = to_tf32(a.x); QPs[row][q*4+1] = to_tf32(a.y);
        QPs[row][q*4+2] = to_tf32(a.z); QPs[row][q*4+3] = to_tf32(a.w);
    }
    __syncthreads();

    uint32_t aq[8][4];
    #pragma unroll
    for (int ks = 0; ks < 8; ks++) {
        int r0 = w * 16 + gr;
        aq[ks][0] = __float_as_uint(QPs[r0    ][8*ks + gc    ]);
        aq[ks][1] = __float_as_uint(QPs[r0 + 8][8*ks + gc    ]);
        aq[ks][2] = __float_as_uint(QPs[r0    ][8*ks + gc + 4]);
        aq[ks][3] = __float_as_uint(QPs[r0 + 8][8*ks + gc + 4]);
    }

    float o[8][4];
    #pragma unroll
    for (int jd = 0; jd < 8; jd++)
        #pragma unroll
        for (int r = 0; r < 4; r++) o[jd][r] = 0.0f;

    float m0 = -1e30f, m1 = -1e30f, l0 = 0.0f, l1 = 0.0f;
    const int rowg = q0 + w * 16 + gr;

    for (int kt = 0; kt < 8; kt++) {
        // Load K and V tiles (tf32). Sync at loop end protects prior reads.
        #pragma unroll
        for (int r = 0; r < 8; r++) {
            int idx = tid + 128 * r;
            int row = idx >> 4;
            int q   = idx & 15;
            float4 kv = *(const float4*)(Kp + (size_t)(kt*64 + row) * D_ + q * 4);
            Ks[row][q*4+0] = to_tf32(kv.x); Ks[row][q*4+1] = to_tf32(kv.y);
            Ks[row][q*4+2] = to_tf32(kv.z); Ks[row][q*4+3] = to_tf32(kv.w);
            float4 vv = *(const float4*)(Vp + (size_t)(kt*64 + row) * D_ + q * 4);
            Vs[row][q*4+0] = to_tf32(vv.x); Vs[row][q*4+1] = to_tf32(vv.y);
            Vs[row][q*4+2] = to_tf32(vv.z); Vs[row][q*4+3] = to_tf32(vv.w);
        }
        __syncthreads();

        // S = Q @ K^T  (warp: 16 rows x 64 cols)
        float s[8][4];
        #pragma unroll
        for (int jn = 0; jn < 8; jn++) {
            #pragma unroll
            for (int r = 0; r < 4; r++) s[jn][r] = 0.0f;
            #pragma unroll
            for (int ks = 0; ks < 8; ks++) {
                uint32_t bv[2];
                bv[0] = __float_as_uint(Ks[jn*8 + gr][8*ks + gc    ]);
                bv[1] = __float_as_uint(Ks[jn*8 + gr][8*ks + gc + 4]);
                mma_tf32(s[jn], aq[ks], bv);
            }
        }

        // scale + mask + write scores + row max
        float mx0 = -1e30f, mx1 = -1e30f;
        #pragma unroll
        for (int jn = 0; jn < 8; jn++) {
            int col = kt*64 + jn*8 + gc*2;
            float mv0 = mrow[col], mv1 = mrow[col + 1];
            s[jn][0] = s[jn][0]*0.125f + mv0;  s[jn][1] = s[jn][1]*0.125f + mv1;
            s[jn][2] = s[jn][2]*0.125f + mv0;  s[jn][3] = s[jn][3]*0.125f + mv1;
            *(float2*)(sout + (size_t)rowg       * S_ + col) = make_float2(s[jn][0], s[jn][1]);
            *(float2*)(sout + (size_t)(rowg + 8) * S_ + col) = make_float2(s[jn][2], s[jn][3]);
            mx0 = fmaxf(mx0, fmaxf(s[jn][0], s[jn][1]));
            mx1 = fmaxf(mx1, fmaxf(s[jn][2], s[jn][3]));
        }
        mx0 = fmaxf(mx0, __shfl_xor_sync(0xffffffffu, mx0, 1));
        mx0 = fmaxf(mx0, __shfl_xor_sync(0xffffffffu, mx0, 2));
        mx1 = fmaxf(mx1, __shfl_xor_sync(0xffffffffu, mx1, 1));
        mx1 = fmaxf(mx1, __shfl_xor_sync(0xffffffffu, mx1, 2));

        float mn0 = fmaxf(m0, mx0), mn1 = fmaxf(m1, mx1);
        float sc0 = __expf(m0 - mn0), sc1 = __expf(m1 - mn1);

        // exp + P store (tf32) + row sum
        float ps0 = 0.0f, ps1 = 0.0f;
        #pragma unroll
        for (int jn = 0; jn < 8; jn++) {
            float p0 = __expf(s[jn][0] - mn0), p1 = __expf(s[jn][1] - mn0);
            float p2 = __expf(s[jn][2] - mn1), p3 = __expf(s[jn][3] - mn1);
            ps0 += p0 + p1;  ps1 += p2 + p3;
            int col = jn*8 + gc*2;
            int r0  = w*16 + gr;
            *(float2*)&QPs[r0    ][col] = make_float2(to_tf32(p0), to_tf32(p1));
            *(float2*)&QPs[r0 + 8][col] = make_float2(to_tf32(p2), to_tf32(p3));
        }
        ps0 += __shfl_xor_sync(0xffffffffu, ps0, 1);
        ps0 += __shfl_xor_sync(0xffffffffu, ps0, 2);
        ps1 += __shfl_xor_sync(0xffffffffu, ps1, 1);
        ps1 += __shfl_xor_sync(0xffffffffu, ps1, 2);
        l0 = l0 * sc0 + ps0;  l1 = l1 * sc1 + ps1;
        m0 = mn0;  m1 = mn1;

        #pragma unroll
        for (int jd = 0; jd < 8; jd++) {
            o[jd][0] *= sc0;  o[jd][1] *= sc0;
            o[jd][2] *= sc1;  o[jd][3] *= sc1;
        }
        __syncwarp();   // P written/read only within this warp's rows

        // O += P @ V   (A from QPs, B = V^T from Vs)
        #pragma unroll
        for (int ks = 0; ks < 8; ks++) {
            uint32_t ap[4];
            int r0 = w*16 + gr;
            ap[0] = __float_as_uint(QPs[r0    ][8*ks + gc    ]);
            ap[1] = __float_as_uint(QPs[r0 + 8][8*ks + gc    ]);
            ap[2] = __float_as_uint(QPs[r0    ][8*ks + gc + 4]);
            ap[3] = __float_as_uint(QPs[r0 + 8][8*ks + gc + 4]);
            #pragma unroll
            for (int jd = 0; jd < 8; jd++) {
                uint32_t bv[2];
                bv[0] = __float_as_uint(Vs[8*ks + gc    ][jd*8 + gr]);
                bv[1] = __float_as_uint(Vs[8*ks + gc + 4][jd*8 + gr]);
                mma_tf32(o[jd], ap, bv);
            }
        }
        __syncthreads();   // all warps done with Ks/Vs before next-iter loads
    }

    // Final normalize + write ctx [B,S,H*D]
    float i0 = 1.0f / l0, i1 = 1.0f / l1;
    #pragma unroll
    for (int jd = 0; jd < 8; jd++) {
        int d = jd*8 + gc*2;
        float* op = ctx + ((size_t)(b * S_ + rowg) * HID_ + h * D_ + d);
        *(float2*)op              = make_float2(o[jd][0] * i0, o[jd][1] * i0);
        *(float2*)(op + 8 * HID_) = make_float2(o[jd][2] * i1, o[jd][3] * i1);
    }
}

// ---------------------------------------------------------------------------
extern "C" void kernel_launch(void* const* d_in, const int* in_sizes, int n_in,
                              void* d_out, int out_size)
{
    const float* hid  = (const float*)d_in[0];
    const float* mask = (const float*)d_in[1];
    const float* Wq   = (const float*)d_in[2];
    const float* bq   = (const float*)d_in[3];
    const float* Wk   = (const float*)d_in[4];
    const float* bk   = (const float*)d_in[5];
    const float* Wv   = (const float*)d_in[6];
    const float* bv   = (const float*)d_in[7];
    float* out = (float*)d_out;

    // 1) Q,K,V projections (3xTF32 MMA, split-at-load)
    qkv_mma<<<dim3(HID_ / 64, BS_ / 128, 3), 256>>>(hid, Wq, bq, Wk, bk, Wv, bv);

    // 2) qq / kk / vv self-similarity scores
    scores_sim<<<dim3(S_ / 128, S_ / 64, 3 * BH_), 256>>>(mask, out + CTX_ELEMS);

    // 3) fused qk scores + softmax + P@V -> scores(qk) region + ctx
    flash_attn<<<dim3(S_ / 64, BH_), 128>>>(mask, out + CTX_ELEMS, out);
}